// round 14
// baseline (speedup 1.0000x reference)
#include <cuda_runtime.h>
#include <cstdint>
#include <cstddef>

// Problem dims (fixed per reference)
#define BB 256
#define TT 512
#define II 64
#define HH 128
#define GG 512   // 4*H

typedef unsigned long long ull;

// Scratch for precomputed input-gate projections: [B, T, 4H] fp32 = 256 MB.
__device__ float g_xg[(size_t)BB * TT * GG];

__device__ __forceinline__ float fsig(float x) {
    return __fdividef(1.f, 1.f + __expf(-x));
}
__device__ __forceinline__ float ftanh(float x) {
    float e = __expf(2.f * x);
    return 1.f - __fdividef(2.f, e + 1.f);
}

// Packed f32x2 ops (sm_103a; ptxas never auto-fuses these)
__device__ __forceinline__ ull fma2(ull a, ull b, ull c) {
    ull d;
    asm("fma.rn.f32x2 %0, %1, %2, %3;" : "=l"(d) : "l"(a), "l"(b), "l"(c));
    return d;
}
__device__ __forceinline__ ull add2(ull a, ull b) {
    ull d;
    asm("add.rn.f32x2 %0, %1, %2;" : "=l"(d) : "l"(a), "l"(b));
    return d;
}
__device__ __forceinline__ ull pack2(float x, float y) {
    ull r;
    asm("mov.b64 %0, {%1, %2};" : "=l"(r) : "f"(x), "f"(y));
    return r;
}
__device__ __forceinline__ float hsum2(ull a) {
    uint2 u = *reinterpret_cast<uint2*>(&a);
    return __uint_as_float(u.x) + __uint_as_float(u.y);
}

#define BAR_SYNC(id, cnt)   asm volatile("bar.sync %0, %1;"   :: "r"(id), "r"(cnt) : "memory")

// ---------------------------------------------------------------------------
// Kernel 1: x_gates GEMM v3 — A-DUPLICATED smem, n-pair-packed accumulators.
// Zero pack2 in the inner loop: b = natural ull read of adjacent Ws floats;
// a = {x,x} dup stored once at staging. NH=256 n-split, 296 blocks = one wave
// at 2 blocks/SM (~99KB smem). LDG->reg prefetch double-buffers the X tile.
// ---------------------------------------------------------------------------
#define NTILES 2048
#define NH 256                   // n-half width
#define WS 260                   // Ws float stride (pad)
#define XDS 66                   // Xs-dup ull stride (64 m + pad)

__global__ __launch_bounds__(256, 2) void xg_gemm(
    const float* __restrict__ X,
    const float* __restrict__ Wih,
    const float* __restrict__ bih,
    const float* __restrict__ bhh)
{
    extern __shared__ __align__(16) float sm[];
    float* Ws = sm;                              // [64][260] natural floats
    float* bs = Ws + 64 * WS;                    // [256]
    ull*   Xd = (ull*)(bs + NH);                 // [64][66] dup ulls (16B-aligned)

    const int tid    = threadIdx.x;
    const int nhalf  = blockIdx.x & 1;
    const int bstart = blockIdx.x >> 1;          // 0..147
    const int ng0    = nhalf * NH;

    bs[tid] = bih[ng0 + tid] + bhh[ng0 + tid];
    for (int idx = tid; idx < NH * 64; idx += 256) {
        int n = idx >> 6, k = idx & 63;
        Ws[k * WS + n] = Wih[(ng0 + n) * II + k];
    }

    const int ni = tid & 31, mi = tid >> 5;
    const int nb = ni * 8,  mb = mi * 8;         // 8 n (4 pairs) x 8 m per thread

    // Staging mapping: thread -> X row ms = tid>>2, k-quad base ks = (tid&3)*4
    const int ms = tid >> 2;
    const int ks = (tid & 3) * 4;

    float xr[16];
    int tile = bstart;
    if (tile < NTILES) {
        #pragma unroll
        for (int i = 0; i < 4; i++)
            *(float4*)&xr[4 * i] =
                *(const float4*)&X[(size_t)(tile * 64 + ms) * II + ks + 16 * i];
    }

    for (; tile < NTILES; tile += 148) {
        __syncthreads();   // previous tile's compute done reading Xd
        #pragma unroll
        for (int i = 0; i < 16; i++) {
            int kk = ks + (i & 3) + 16 * (i >> 2);
            Xd[kk * XDS + ms] = pack2(xr[i], xr[i]);
        }
        __syncthreads();   // Xd ready (first iter: also Ws/bs)

        // Prefetch next tile's X into registers (hidden under compute)
        int ntile = tile + 148;
        if (ntile < NTILES) {
            #pragma unroll
            for (int i = 0; i < 4; i++)
                *(float4*)&xr[4 * i] =
                    *(const float4*)&X[(size_t)(ntile * 64 + ms) * II + ks + 16 * i];
        }

        // acc[m][np]: packed gate-pair {nb+2np, nb+2np+1} for row mb+m
        const ull* bsu = (const ull*)bs;
        ull acc[8][4];
        #pragma unroll
        for (int np = 0; np < 4; np++) {
            ull bb = bsu[nb / 2 + np];
            #pragma unroll
            for (int m = 0; m < 8; m++) acc[m][np] = bb;
        }

        #pragma unroll 8
        for (int k = 0; k < 64; k++) {
            ulonglong2 a01 = *(const ulonglong2*)&Xd[k * XDS + mb];
            ulonglong2 a23 = *(const ulonglong2*)&Xd[k * XDS + mb + 2];
            ulonglong2 a45 = *(const ulonglong2*)&Xd[k * XDS + mb + 4];
            ulonglong2 a67 = *(const ulonglong2*)&Xd[k * XDS + mb + 6];
            ull a[8] = {a01.x, a01.y, a23.x, a23.y, a45.x, a45.y, a67.x, a67.y};
            ulonglong2 b01 = *(const ulonglong2*)&Ws[k * WS + nb];      // pairs {nb,nb+1},{nb+2,nb+3}
            ulonglong2 b23 = *(const ulonglong2*)&Ws[k * WS + nb + 4];
            ull bv[4] = {b01.x, b01.y, b23.x, b23.y};
            #pragma unroll
            for (int m = 0; m < 8; m++)
                #pragma unroll
                for (int np = 0; np < 4; np++)
                    acc[m][np] = fma2(a[m], bv[np], acc[m][np]);
        }

        #pragma unroll
        for (int m = 0; m < 8; m++) {
            size_t row = (size_t)(tile * 64 + mb + m);
            ulonglong2* o = (ulonglong2*)&g_xg[row * GG + ng0 + nb];
            ulonglong2 v0; v0.x = acc[m][0]; v0.y = acc[m][1];
            ulonglong2 v1; v1.x = acc[m][2]; v1.y = acc[m][3];
            o[0] = v0;
            o[1] = v1;
        }
    }
}

// ---------------------------------------------------------------------------
// Kernel 2: LSTM scan — EXACT R10/R13 version (proven best: 630-634 us).
// ---------------------------------------------------------------------------
#define KREG 80                  // k-values per gate held in registers
#define QSH  12                  // (128-KREG)/4 : ulonglong2 smem weight loads

__global__ __launch_bounds__(256, 1) void lstm_scan(
    const float* __restrict__ hprev,
    const float* __restrict__ cprev,
    const float* __restrict__ Whh,
    float* __restrict__ out)
{
    extern __shared__ __align__(16) float smdyn[];
    ulonglong2* wA = (ulonglong2*)smdyn;         // [QSH][256]
    ulonglong2* wB = wA + QSH * 256;             // [QSH][256]
    float* hbuf = (float*)(wB + QSH * 256);      // [2 buf][2 batch][128]
    float* gsm  = hbuf + 2 * 2 * 128;            // [2][512]

    const int tid = threadIdx.x;
    const int b0  = blockIdx.x * 2;
    const int gA  = tid;
    const int gB  = tid + 256;
    const int barid = 1 + ((tid >> 5) & 3);      // 2-warp group {w, w+4}

    #pragma unroll
    for (int q = 0; q < QSH; q++) {
        wA[q * 256 + tid] = *(const ulonglong2*)&Whh[gA * HH + KREG + 4 * q];
        wB[q * 256 + tid] = *(const ulonglong2*)&Whh[gB * HH + KREG + 4 * q];
    }

    ull wrA[KREG / 2], wrB[KREG / 2];
    #pragma unroll
    for (int p = 0; p < KREG / 2; p++) {
        wrA[p] = *(const ull*)&Whh[gA * HH + 2 * p];
        wrB[p] = *(const ull*)&Whh[gB * HH + 2 * p];
    }

    float* hc0 = hbuf;             // current, batch 0
    float* hc1 = hbuf + 128;       // current, batch 1
    float* hn0 = hbuf + 256;       // next,    batch 0
    float* hn1 = hbuf + 384;       // next,    batch 1

    const int b = tid >> 7, j = tid & 127;
    float h = hprev[(b0 + b) * HH + j];
    float c = cprev[(b0 + b) * HH + j];
    (b ? hc1 : hc0)[j] = h;
    __syncthreads();

    const float* xb0 = g_xg + (size_t)b0 * TT * GG;
    const float* xb1 = xb0 + (size_t)TT * GG;

    float x00 = xb0[tid], x01 = xb0[256 + tid];
    float x10 = xb1[tid], x11 = xb1[256 + tid];

    for (int t = 0; t < TT; t++) {
        size_t noff = (size_t)(t + 1 < TT ? t + 1 : t) * GG;
        float n00 = xb0[noff + tid], n01 = xb0[noff + 256 + tid];
        float n10 = xb1[noff + tid], n11 = xb1[noff + 256 + tid];

        ull aA0x = 0, aA0y = 0, aA1x = 0, aA1y = 0;
        ull aB0x = 0, aB0y = 0, aB1x = 0, aB1y = 0;

        #pragma unroll
        for (int q = 0; q < KREG / 4; q++) {
            ulonglong2 h0 = *(const ulonglong2*)&hc0[4 * q];
            ulonglong2 h1 = *(const ulonglong2*)&hc1[4 * q];
            ull w0 = wrA[2 * q], w1 = wrA[2 * q + 1];
            ull v0 = wrB[2 * q], v1 = wrB[2 * q + 1];
            aA0x = fma2(w0, h0.x, aA0x);  aA0y = fma2(w1, h0.y, aA0y);
            aA1x = fma2(w0, h1.x, aA1x);  aA1y = fma2(w1, h1.y, aA1y);
            aB0x = fma2(v0, h0.x, aB0x);  aB0y = fma2(v1, h0.y, aB0y);
            aB1x = fma2(v0, h1.x, aB1x);  aB1y = fma2(v1, h1.y, aB1y);
        }
        #pragma unroll
        for (int q = 0; q < QSH; q++) {
            ulonglong2 h0 = *(const ulonglong2*)&hc0[KREG + 4 * q];
            ulonglong2 h1 = *(const ulonglong2*)&hc1[KREG + 4 * q];
            ulonglong2 wa = wA[q * 256 + tid];
            ulonglong2 wb = wB[q * 256 + tid];
            aA0x = fma2(wa.x, h0.x, aA0x);  aA0y = fma2(wa.y, h0.y, aA0y);
            aA1x = fma2(wa.x, h1.x, aA1x);  aA1y = fma2(wa.y, h1.y, aA1y);
            aB0x = fma2(wb.x, h0.x, aB0x);  aB0y = fma2(wb.y, h0.y, aB0y);
            aB1x = fma2(wb.x, h1.x, aB1x);  aB1y = fma2(wb.y, h1.y, aB1y);
        }

        gsm[tid]             = x00 + hsum2(add2(aA0x, aA0y));
        gsm[256 + tid]       = x01 + hsum2(add2(aB0x, aB0y));
        gsm[512 + tid]       = x10 + hsum2(add2(aA1x, aA1y));
        gsm[512 + 256 + tid] = x11 + hsum2(add2(aB1x, aB1y));

        BAR_SYNC(barid, 64);

        {
            const float* gb = gsm + b * 512;
            float ig = fsig(gb[j]);             // PyTorch order: i, f, g, o
            float fg = fsig(gb[j + 128]);
            float gg = ftanh(gb[j + 256]);
            float og = fsig(gb[j + 384]);
            c = fg * c + ig * gg;
            h = og * ftanh(c);
            (b ? hn1 : hn0)[j] = h;
            out[((size_t)(b0 + b) * TT + t) * HH + j] = h;
        }
        __syncthreads();

        float* s0 = hc0; hc0 = hn0; hn0 = s0;
        float* s1 = hc1; hc1 = hn1; hn1 = s1;

        x00 = n00; x01 = n01; x10 = n10; x11 = n11;
    }

    {
        size_t base = (size_t)BB * TT * HH;
        out[base + (b0 + b) * HH + j] = h;
        out[base + (size_t)BB * HH + (b0 + b) * HH + j] = c;
    }
}

// ---------------------------------------------------------------------------
extern "C" void kernel_launch(void* const* d_in, const int* in_sizes, int n_in,
                              void* d_out, int out_size)
{
    const float* inputs = (const float*)d_in[0];
    const float* hprev  = (const float*)d_in[1];
    const float* cprev  = (const float*)d_in[2];
    const float* Wih    = (const float*)d_in[3];
    const float* Whh    = (const float*)d_in[4];
    const float* bih    = (const float*)d_in[5];
    const float* bhh    = (const float*)d_in[6];
    float* out = (float*)d_out;
    (void)in_sizes; (void)n_in; (void)out_size;

    const size_t smem1 = (size_t)(64 * WS + NH) * sizeof(float)
                       + (size_t)(64 * XDS) * sizeof(ull);                // ~99 KB
    const size_t smem2 = (size_t)(2 * QSH * 256) * sizeof(ulonglong2)
                       + (size_t)(2 * 2 * 128 + 2 * 512) * sizeof(float); // ~104 KB
    cudaFuncSetAttribute(xg_gemm,   cudaFuncAttributeMaxDynamicSharedMemorySize, (int)smem1);
    cudaFuncSetAttribute(lstm_scan, cudaFuncAttributeMaxDynamicSharedMemorySize, (int)smem2);

    xg_gemm  <<<296, 256, smem1>>>(inputs, Wih, bih, bhh);
    lstm_scan<<<128, 256, smem2>>>(hprev, cprev, Whh, out);
}

// round 15
// speedup vs baseline: 1.0766x; 1.0766x over previous
#include <cuda_runtime.h>
#include <cstdint>
#include <cstddef>

// Problem dims (fixed per reference)
#define BB 256
#define TT 512
#define II 64
#define HH 128
#define GG 512   // 4*H

typedef unsigned long long ull;

// Scratch for precomputed input-gate projections: [B, T, 4H] fp32 = 256 MB.
__device__ float g_xg[(size_t)BB * TT * GG];

__device__ __forceinline__ float fsig(float x) {
    return __fdividef(1.f, 1.f + __expf(-x));
}
__device__ __forceinline__ float ftanh(float x) {
    float e = __expf(2.f * x);
    return 1.f - __fdividef(2.f, e + 1.f);
}

__device__ __forceinline__ ull fma2(ull a, ull b, ull c) {
    ull d;
    asm("fma.rn.f32x2 %0, %1, %2, %3;" : "=l"(d) : "l"(a), "l"(b), "l"(c));
    return d;
}
__device__ __forceinline__ ull add2(ull a, ull b) {
    ull d;
    asm("add.rn.f32x2 %0, %1, %2;" : "=l"(d) : "l"(a), "l"(b));
    return d;
}
__device__ __forceinline__ float hsum2(ull a) {
    uint2 u = *reinterpret_cast<uint2*>(&a);
    return __uint_as_float(u.x) + __uint_as_float(u.y);
}

// tf32 conversion: hi = rna_tf32(x) (bit-pattern is a valid f32), lo = rna_tf32(x - hi)
__device__ __forceinline__ unsigned cvt_tf32(float x) {
    unsigned r;
    asm("cvt.rna.tf32.f32 %0, %1;" : "=r"(r) : "f"(x));
    return r;
}

__device__ __forceinline__ void mma_tf32(
    float& d0, float& d1, float& d2, float& d3,
    unsigned a0, unsigned a1, unsigned a2, unsigned a3,
    unsigned b0, unsigned b1)
{
    asm volatile(
        "mma.sync.aligned.m16n8k8.row.col.f32.tf32.tf32.f32 "
        "{%0,%1,%2,%3}, {%4,%5,%6,%7}, {%8,%9}, {%0,%1,%2,%3};"
        : "+f"(d0), "+f"(d1), "+f"(d2), "+f"(d3)
        : "r"(a0), "r"(a1), "r"(a2), "r"(a3), "r"(b0), "r"(b1));
}

#define BAR_SYNC(id, cnt)   asm volatile("bar.sync %0, %1;"   :: "r"(id), "r"(cnt) : "memory")

// ---------------------------------------------------------------------------
// Kernel 1: x_gates GEMM — tf32 SPLIT-PRECISION mma.sync (tensor path).
// D = X @ W^T + bias with x = xhi + xlo, w = whi + wlo (rna tf32 splits);
// D accumulates hi*hi + hi*lo + lo*hi in fp32 (error ~2^-24, ~fp32).
// 148 persistent blocks x 256 threads. Block tile M=128 x NH=256 x K=64.
// Warp (wm = w&3, wn = w>>2): m32 x n128; per k-step 96 MMAs vs 80 LDS.
// W staged per n-half (k-major [64][264] tf32 hi/lo), X per m-tile ([128][68]).
// ---------------------------------------------------------------------------
#define NHW 256                // n-half width
#define WTS 264                // W k-major stride (n + pad)
#define XTS 68                 // X m-major stride (k + pad)

__global__ __launch_bounds__(256, 1) void xg_gemm(
    const float* __restrict__ X,
    const float* __restrict__ Wih,
    const float* __restrict__ bih,
    const float* __restrict__ bhh)
{
    extern __shared__ __align__(16) float sm[];
    float* Whi = sm;                       // [64][264] tf32 bits as floats
    float* Wlo = Whi + 64 * WTS;
    float* Xhi = Wlo + 64 * WTS;           // [128][68]
    float* Xlo = Xhi + 128 * XTS;
    float* bs  = Xlo + 128 * XTS;          // [256]

    const int tid  = threadIdx.x;
    const int lane = tid & 31;
    const int w    = tid >> 5;
    const int wm   = w & 3;                // m32 group
    const int wn   = w >> 2;               // n128 group
    const int grp  = lane >> 2;            // groupID (0..7)
    const int tig  = lane & 3;             // threadID_in_group (0..3)

    int staged_half = -1;

    for (int task = blockIdx.x; task < 2048; task += 148) {
        const int half = task >> 10;
        const int mt   = task & 1023;
        const int ng0  = half * NHW;
        const int m0   = mt * 128;

        __syncthreads();   // previous tile's readers done

        // ---- stage W half (tf32 hi/lo, k-major) on half change ----
        if (half != staged_half) {
            staged_half = half;
            const float* wrow = &Wih[(ng0 + tid) * II];   // thread owns gate n=tid
            #pragma unroll
            for (int kq = 0; kq < 16; kq++) {
                float4 v = *(const float4*)&wrow[4 * kq];
                float vv[4] = {v.x, v.y, v.z, v.w};
                #pragma unroll
                for (int e = 0; e < 4; e++) {
                    int k = 4 * kq + e;
                    unsigned hb = cvt_tf32(vv[e]);
                    float hf = __uint_as_float(hb);
                    unsigned lb = cvt_tf32(vv[e] - hf);
                    Whi[k * WTS + tid] = __uint_as_float(hb);
                    Wlo[k * WTS + tid] = __uint_as_float(lb);
                }
            }
            bs[tid] = bih[ng0 + tid] + bhh[ng0 + tid];
        }

        // ---- stage X tile (tf32 hi/lo, m-major) ----
        #pragma unroll
        for (int i = 0; i < 8; i++) {
            int idx = tid + 256 * i;       // 0..2047 float4 slots
            int r = idx >> 4, q = idx & 15;
            float4 v = *(const float4*)&X[(size_t)(m0 + r) * II + 4 * q];
            float vv[4] = {v.x, v.y, v.z, v.w};
            float hi4[4], lo4[4];
            #pragma unroll
            for (int e = 0; e < 4; e++) {
                unsigned hb = cvt_tf32(vv[e]);
                float hf = __uint_as_float(hb);
                hi4[e] = hf;
                lo4[e] = __uint_as_float(cvt_tf32(vv[e] - hf));
            }
            *(float4*)&Xhi[r * XTS + 4 * q] = make_float4(hi4[0], hi4[1], hi4[2], hi4[3]);
            *(float4*)&Xlo[r * XTS + 4 * q] = make_float4(lo4[0], lo4[1], lo4[2], lo4[3]);
        }
        __syncthreads();

        // ---- compute: acc[mf][nf][4], m-frag rows 32wm+16mf, n-frag 8nf ----
        float acc[2][16][4];
        #pragma unroll
        for (int mf = 0; mf < 2; mf++)
            #pragma unroll
            for (int nf = 0; nf < 16; nf++)
                #pragma unroll
                for (int e = 0; e < 4; e++) acc[mf][nf][e] = 0.f;

        for (int ks = 0; ks < 8; ks++) {
            const int k0 = 8 * ks;
            // A fragments (row-major m16k8): a0(row grp, col tig), a1(+8 row),
            // a2(col tig+4), a3(row+8, col+4); per m-frag, hi & lo.
            unsigned Ah[2][4], Al[2][4];
            #pragma unroll
            for (int mf = 0; mf < 2; mf++) {
                int rbase = 32 * wm + 16 * mf + grp;
                const float* xh = &Xhi[rbase * XTS + k0 + tig];
                const float* xl = &Xlo[rbase * XTS + k0 + tig];
                Ah[mf][0] = __float_as_uint(xh[0]);
                Ah[mf][1] = __float_as_uint(xh[8 * XTS]);
                Ah[mf][2] = __float_as_uint(xh[4]);
                Ah[mf][3] = __float_as_uint(xh[8 * XTS + 4]);
                Al[mf][0] = __float_as_uint(xl[0]);
                Al[mf][1] = __float_as_uint(xl[8 * XTS]);
                Al[mf][2] = __float_as_uint(xl[4]);
                Al[mf][3] = __float_as_uint(xl[8 * XTS + 4]);
            }
            #pragma unroll
            for (int nf = 0; nf < 16; nf++) {
                // B fragments (col-major k8n8): b0(row tig, col grp), b1(row tig+4)
                int nbase = 128 * wn + 8 * nf + grp;
                unsigned bh0 = __float_as_uint(Whi[(k0 + tig) * WTS + nbase]);
                unsigned bh1 = __float_as_uint(Whi[(k0 + tig + 4) * WTS + nbase]);
                unsigned bl0 = __float_as_uint(Wlo[(k0 + tig) * WTS + nbase]);
                unsigned bl1 = __float_as_uint(Wlo[(k0 + tig + 4) * WTS + nbase]);
                #pragma unroll
                for (int mf = 0; mf < 2; mf++) {
                    float* d = acc[mf][nf];
                    mma_tf32(d[0], d[1], d[2], d[3],
                             Ah[mf][0], Ah[mf][1], Ah[mf][2], Ah[mf][3], bh0, bh1);
                    mma_tf32(d[0], d[1], d[2], d[3],
                             Ah[mf][0], Ah[mf][1], Ah[mf][2], Ah[mf][3], bl0, bl1);
                    mma_tf32(d[0], d[1], d[2], d[3],
                             Al[mf][0], Al[mf][1], Al[mf][2], Al[mf][3], bh0, bh1);
                }
            }
        }

        // ---- epilogue: add bias, store fp32 ----
        #pragma unroll
        for (int mf = 0; mf < 2; mf++) {
            #pragma unroll
            for (int nf = 0; nf < 16; nf++) {
                int row = m0 + 32 * wm + 16 * mf + grp;
                int c   = 128 * wn + 8 * nf + 2 * tig;     // within half
                float2 bv = *(const float2*)&bs[c];
                const float* d = acc[mf][nf];
                float2 v0 = make_float2(d[0] + bv.x, d[1] + bv.y);
                float2 v1 = make_float2(d[2] + bv.x, d[3] + bv.y);
                *(float2*)&g_xg[(size_t)row * GG + ng0 + c]       = v0;
                *(float2*)&g_xg[(size_t)(row + 8) * GG + ng0 + c] = v1;
            }
        }
    }
}

// ---------------------------------------------------------------------------
// Kernel 2: LSTM scan — EXACT R10/R14 version (proven best: 628-634 us).
// ---------------------------------------------------------------------------
#define KREG 80                  // k-values per gate held in registers
#define QSH  12                  // (128-KREG)/4 : ulonglong2 smem weight loads

__global__ __launch_bounds__(256, 1) void lstm_scan(
    const float* __restrict__ hprev,
    const float* __restrict__ cprev,
    const float* __restrict__ Whh,
    float* __restrict__ out)
{
    extern __shared__ __align__(16) float smdyn[];
    ulonglong2* wA = (ulonglong2*)smdyn;         // [QSH][256]
    ulonglong2* wB = wA + QSH * 256;             // [QSH][256]
    float* hbuf = (float*)(wB + QSH * 256);      // [2 buf][2 batch][128]
    float* gsm  = hbuf + 2 * 2 * 128;            // [2][512]

    const int tid = threadIdx.x;
    const int b0  = blockIdx.x * 2;
    const int gA  = tid;
    const int gB  = tid + 256;
    const int barid = 1 + ((tid >> 5) & 3);      // 2-warp group {w, w+4}

    #pragma unroll
    for (int q = 0; q < QSH; q++) {
        wA[q * 256 + tid] = *(const ulonglong2*)&Whh[gA * HH + KREG + 4 * q];
        wB[q * 256 + tid] = *(const ulonglong2*)&Whh[gB * HH + KREG + 4 * q];
    }

    ull wrA[KREG / 2], wrB[KREG / 2];
    #pragma unroll
    for (int p = 0; p < KREG / 2; p++) {
        wrA[p] = *(const ull*)&Whh[gA * HH + 2 * p];
        wrB[p] = *(const ull*)&Whh[gB * HH + 2 * p];
    }

    float* hc0 = hbuf;             // current, batch 0
    float* hc1 = hbuf + 128;       // current, batch 1
    float* hn0 = hbuf + 256;       // next,    batch 0
    float* hn1 = hbuf + 384;       // next,    batch 1

    const int b = tid >> 7, j = tid & 127;
    float h = hprev[(b0 + b) * HH + j];
    float c = cprev[(b0 + b) * HH + j];
    (b ? hc1 : hc0)[j] = h;
    __syncthreads();

    const float* xb0 = g_xg + (size_t)b0 * TT * GG;
    const float* xb1 = xb0 + (size_t)TT * GG;

    float x00 = xb0[tid], x01 = xb0[256 + tid];
    float x10 = xb1[tid], x11 = xb1[256 + tid];

    for (int t = 0; t < TT; t++) {
        size_t noff = (size_t)(t + 1 < TT ? t + 1 : t) * GG;
        float n00 = xb0[noff + tid], n01 = xb0[noff + 256 + tid];
        float n10 = xb1[noff + tid], n11 = xb1[noff + 256 + tid];

        ull aA0x = 0, aA0y = 0, aA1x = 0, aA1y = 0;
        ull aB0x = 0, aB0y = 0, aB1x = 0, aB1y = 0;

        #pragma unroll
        for (int q = 0; q < KREG / 4; q++) {
            ulonglong2 h0 = *(const ulonglong2*)&hc0[4 * q];
            ulonglong2 h1 = *(const ulonglong2*)&hc1[4 * q];
            ull w0 = wrA[2 * q], w1 = wrA[2 * q + 1];
            ull v0 = wrB[2 * q], v1 = wrB[2 * q + 1];
            aA0x = fma2(w0, h0.x, aA0x);  aA0y = fma2(w1, h0.y, aA0y);
            aA1x = fma2(w0, h1.x, aA1x);  aA1y = fma2(w1, h1.y, aA1y);
            aB0x = fma2(v0, h0.x, aB0x);  aB0y = fma2(v1, h0.y, aB0y);
            aB1x = fma2(v0, h1.x, aB1x);  aB1y = fma2(v1, h1.y, aB1y);
        }
        #pragma unroll
        for (int q = 0; q < QSH; q++) {
            ulonglong2 h0 = *(const ulonglong2*)&hc0[KREG + 4 * q];
            ulonglong2 h1 = *(const ulonglong2*)&hc1[KREG + 4 * q];
            ulonglong2 wa = wA[q * 256 + tid];
            ulonglong2 wb = wB[q * 256 + tid];
            aA0x = fma2(wa.x, h0.x, aA0x);  aA0y = fma2(wa.y, h0.y, aA0y);
            aA1x = fma2(wa.x, h1.x, aA1x);  aA1y = fma2(wa.y, h1.y, aA1y);
            aB0x = fma2(wb.x, h0.x, aB0x);  aB0y = fma2(wb.y, h0.y, aB0y);
            aB1x = fma2(wb.x, h1.x, aB1x);  aB1y = fma2(wb.y, h1.y, aB1y);
        }

        gsm[tid]             = x00 + hsum2(add2(aA0x, aA0y));
        gsm[256 + tid]       = x01 + hsum2(add2(aB0x, aB0y));
        gsm[512 + tid]       = x10 + hsum2(add2(aA1x, aA1y));
        gsm[512 + 256 + tid] = x11 + hsum2(add2(aB1x, aB1y));

        BAR_SYNC(barid, 64);

        {
            const float* gb = gsm + b * 512;
            float ig = fsig(gb[j]);             // PyTorch order: i, f, g, o
            float fg = fsig(gb[j + 128]);
            float gg = ftanh(gb[j + 256]);
            float og = fsig(gb[j + 384]);
            c = fg * c + ig * gg;
            h = og * ftanh(c);
            (b ? hn1 : hn0)[j] = h;
            out[((size_t)(b0 + b) * TT + t) * HH + j] = h;
        }
        __syncthreads();

        float* s0 = hc0; hc0 = hn0; hn0 = s0;
        float* s1 = hc1; hc1 = hn1; hn1 = s1;

        x00 = n00; x01 = n01; x10 = n10; x11 = n11;
    }

    {
        size_t base = (size_t)BB * TT * HH;
        out[base + (b0 + b) * HH + j] = h;
        out[base + (size_t)BB * HH + (b0 + b) * HH + j] = c;
    }
}

// ---------------------------------------------------------------------------
extern "C" void kernel_launch(void* const* d_in, const int* in_sizes, int n_in,
                              void* d_out, int out_size)
{
    const float* inputs = (const float*)d_in[0];
    const float* hprev  = (const float*)d_in[1];
    const float* cprev  = (const float*)d_in[2];
    const float* Wih    = (const float*)d_in[3];
    const float* Whh    = (const float*)d_in[4];
    const float* bih    = (const float*)d_in[5];
    const float* bhh    = (const float*)d_in[6];
    float* out = (float*)d_out;
    (void)in_sizes; (void)n_in; (void)out_size;

    const size_t smem1 = (size_t)(2 * 64 * WTS + 2 * 128 * XTS + 256) * sizeof(float); // ~202 KB
    const size_t smem2 = (size_t)(2 * QSH * 256) * sizeof(ulonglong2)
                       + (size_t)(2 * 2 * 128 + 2 * 512) * sizeof(float);              // ~104 KB
    cudaFuncSetAttribute(xg_gemm,   cudaFuncAttributeMaxDynamicSharedMemorySize, (int)smem1);
    cudaFuncSetAttribute(lstm_scan, cudaFuncAttributeMaxDynamicSharedMemorySize, (int)smem2);

    xg_gemm  <<<148, 256, smem1>>>(inputs, Wih, bih, bhh);
    lstm_scan<<<128, 256, smem2>>>(hprev, cprev, Whh, out);
}

// round 16
// speedup vs baseline: 1.1267x; 1.0465x over previous
#include <cuda_runtime.h>
#include <cuda_bf16.h>
#include <cstdint>
#include <cstddef>

// Problem dims (fixed per reference)
#define BB 256
#define TT 512
#define II 64
#define HH 128
#define GG 512   // 4*H

typedef unsigned long long ull;

// Scratch for precomputed input-gate projections: [B, T, 4H] fp32 = 256 MB.
__device__ float g_xg[(size_t)BB * TT * GG];

__device__ __forceinline__ float fsig(float x) {
    return __fdividef(1.f, 1.f + __expf(-x));
}
__device__ __forceinline__ float ftanh(float x) {
    float e = __expf(2.f * x);
    return 1.f - __fdividef(2.f, e + 1.f);
}

__device__ __forceinline__ ull fma2(ull a, ull b, ull c) {
    ull d;
    asm("fma.rn.f32x2 %0, %1, %2, %3;" : "=l"(d) : "l"(a), "l"(b), "l"(c));
    return d;
}
__device__ __forceinline__ ull add2(ull a, ull b) {
    ull d;
    asm("add.rn.f32x2 %0, %1, %2;" : "=l"(d) : "l"(a), "l"(b));
    return d;
}
__device__ __forceinline__ float hsum2(ull a) {
    uint2 u = *reinterpret_cast<uint2*>(&a);
    return __uint_as_float(u.x) + __uint_as_float(u.y);
}

__device__ __forceinline__ void mma_bf16(
    float& d0, float& d1, float& d2, float& d3,
    unsigned a0, unsigned a1, unsigned a2, unsigned a3,
    unsigned b0, unsigned b1)
{
    asm volatile(
        "mma.sync.aligned.m16n8k16.row.col.f32.bf16.bf16.f32 "
        "{%0,%1,%2,%3}, {%4,%5,%6,%7}, {%8,%9}, {%0,%1,%2,%3};"
        : "+f"(d0), "+f"(d1), "+f"(d2), "+f"(d3)
        : "r"(a0), "r"(a1), "r"(a2), "r"(a3), "r"(b0), "r"(b1));
}

// Split x into bf16 hi + bf16 lo; pack pairs {k, k+1} (k in low half).
__device__ __forceinline__ void bf16_split2(float x0, float x1,
                                            unsigned& hi, unsigned& lo)
{
    __nv_bfloat16 h0 = __float2bfloat16_rn(x0);
    __nv_bfloat16 h1 = __float2bfloat16_rn(x1);
    __nv_bfloat16 l0 = __float2bfloat16_rn(x0 - __bfloat162float(h0));
    __nv_bfloat16 l1 = __float2bfloat16_rn(x1 - __bfloat162float(h1));
    __nv_bfloat162 hp = __halves2bfloat162(h0, h1);   // h0 in low
    __nv_bfloat162 lp = __halves2bfloat162(l0, l1);
    hi = *reinterpret_cast<unsigned*>(&hp);
    lo = *reinterpret_cast<unsigned*>(&lp);
}

#define BAR_SYNC(id, cnt)   asm volatile("bar.sync %0, %1;"   :: "r"(id), "r"(cnt) : "memory")

// ---------------------------------------------------------------------------
// Kernel 1: x_gates GEMM — bf16 SPLIT-PRECISION m16n8k16 mma.sync.
// D = X@W^T + bias with x = xhi+xlo (bf16): acc hi*hi + hi*lo + lo*hi in fp32;
// dropped lo*lo ~2^-18 rel/term -> output rel err ~1e-5.
// 296 blocks (2/SM) x 256 threads. Block tile M=128 x NQ=128 x K=64.
// Warp (wm=w&3, wn=w>>2): m32 x n64. Per k16-step: A 16 LDS + B 32 LDS,
// 48 MMAs. Smem rows: 32 uint32 pairs + 4 pad (stride%32==4 -> 4*grp+tig
// gives conflict-free fragment loads). W quarter restaged on change only.
// ---------------------------------------------------------------------------
#define NQ 128                 // n-quarter width
#define QS 36                  // uint32 row stride (32 pairs + 4 pad)

__global__ __launch_bounds__(256, 2) void xg_gemm(
    const float* __restrict__ X,
    const float* __restrict__ Wih,
    const float* __restrict__ bih,
    const float* __restrict__ bhh)
{
    extern __shared__ __align__(16) unsigned smu[];
    unsigned* Whi = smu;                   // [128][36]
    unsigned* Wlo = Whi + 128 * QS;
    unsigned* Xhi = Wlo + 128 * QS;        // [128][36]
    unsigned* Xlo = Xhi + 128 * QS;
    float*    bs  = (float*)(Xlo + 128 * QS);   // [128]

    const int tid  = threadIdx.x;
    const int lane = tid & 31;
    const int w    = tid >> 5;
    const int wm   = w & 3;                // m32 group (0..3)
    const int wn   = w >> 2;               // n64 group (0..1)
    const int grp  = lane >> 2;            // 0..7
    const int tig  = lane & 3;             // 0..3

    // Staging mapping: row = tid>>1, k-offset = (tid&1)*32 (16 pairs each)
    const int srow = tid >> 1;
    const int koff = (tid & 1) * 32;
    const int pbase = srow * QS + (koff >> 1);

    int staged_q = -1;

    for (int task = blockIdx.x; task < 4096; task += 296) {
        const int quarter = task >> 10;
        const int m0      = (task & 1023) * 128;
        const int nq0     = quarter * NQ;

        __syncthreads();   // previous tile's fragment readers done

        // ---- stage W quarter (only when it changes) ----
        if (quarter != staged_q) {
            staged_q = quarter;
            const float* wsrc = &Wih[(nq0 + srow) * II + koff];
            #pragma unroll
            for (int i = 0; i < 8; i++) {
                float4 v = *(const float4*)&wsrc[4 * i];
                unsigned h0, l0, h1, l1;
                bf16_split2(v.x, v.y, h0, l0);
                bf16_split2(v.z, v.w, h1, l1);
                Whi[pbase + 2 * i]     = h0;
                Whi[pbase + 2 * i + 1] = h1;
                Wlo[pbase + 2 * i]     = l0;
                Wlo[pbase + 2 * i + 1] = l1;
            }
            if (tid < NQ) bs[tid] = bih[nq0 + tid] + bhh[nq0 + tid];
        }

        // ---- stage X tile ----
        {
            const float* xsrc = &X[(size_t)(m0 + srow) * II + koff];
            #pragma unroll
            for (int i = 0; i < 8; i++) {
                float4 v = *(const float4*)&xsrc[4 * i];
                unsigned h0, l0, h1, l1;
                bf16_split2(v.x, v.y, h0, l0);
                bf16_split2(v.z, v.w, h1, l1);
                Xhi[pbase + 2 * i]     = h0;
                Xhi[pbase + 2 * i + 1] = h1;
                Xlo[pbase + 2 * i]     = l0;
                Xlo[pbase + 2 * i + 1] = l1;
            }
        }
        __syncthreads();

        // ---- compute: acc[mf][nf][4] ----
        float acc[2][8][4];
        #pragma unroll
        for (int mf = 0; mf < 2; mf++)
            #pragma unroll
            for (int nf = 0; nf < 8; nf++)
                #pragma unroll
                for (int e = 0; e < 4; e++) acc[mf][nf][e] = 0.f;

        #pragma unroll
        for (int ks = 0; ks < 4; ks++) {           // k16 steps over K=64
            const int pb = 8 * ks;                 // pair base of this step
            unsigned Ah[2][4], Al[2][4];
            #pragma unroll
            for (int mf = 0; mf < 2; mf++) {
                int r = 32 * wm + 16 * mf + grp;
                const unsigned* xh = &Xhi[r * QS + pb + tig];
                const unsigned* xl = &Xlo[r * QS + pb + tig];
                Ah[mf][0] = xh[0];        Ah[mf][1] = xh[8 * QS];
                Ah[mf][2] = xh[4];        Ah[mf][3] = xh[8 * QS + 4];
                Al[mf][0] = xl[0];        Al[mf][1] = xl[8 * QS];
                Al[mf][2] = xl[4];        Al[mf][3] = xl[8 * QS + 4];
            }
            #pragma unroll
            for (int nf = 0; nf < 8; nf++) {
                int n = 64 * wn + 8 * nf + grp;
                unsigned bh0 = Whi[n * QS + pb + tig];
                unsigned bh1 = Whi[n * QS + pb + tig + 4];
                unsigned bl0 = Wlo[n * QS + pb + tig];
                unsigned bl1 = Wlo[n * QS + pb + tig + 4];
                #pragma unroll
                for (int mf = 0; mf < 2; mf++) {
                    float* d = acc[mf][nf];
                    mma_bf16(d[0], d[1], d[2], d[3],
                             Ah[mf][0], Ah[mf][1], Ah[mf][2], Ah[mf][3], bh0, bh1);
                    mma_bf16(d[0], d[1], d[2], d[3],
                             Ah[mf][0], Ah[mf][1], Ah[mf][2], Ah[mf][3], bl0, bl1);
                    mma_bf16(d[0], d[1], d[2], d[3],
                             Al[mf][0], Al[mf][1], Al[mf][2], Al[mf][3], bh0, bh1);
                }
            }
        }

        // ---- epilogue: add bias, store fp32 ----
        #pragma unroll
        for (int mf = 0; mf < 2; mf++) {
            #pragma unroll
            for (int nf = 0; nf < 8; nf++) {
                int row = m0 + 32 * wm + 16 * mf + grp;
                int c   = 64 * wn + 8 * nf + 2 * tig;     // within quarter
                float2 bv = *(const float2*)&bs[c];
                const float* d = acc[mf][nf];
                float2 v0 = make_float2(d[0] + bv.x, d[1] + bv.y);
                float2 v1 = make_float2(d[2] + bv.x, d[3] + bv.y);
                *(float2*)&g_xg[(size_t)row * GG + nq0 + c]       = v0;
                *(float2*)&g_xg[(size_t)(row + 8) * GG + nq0 + c] = v1;
            }
        }
    }
}

// ---------------------------------------------------------------------------
// Kernel 2: LSTM scan — EXACT R10/R15 version (proven best: 628-634 us).
// ---------------------------------------------------------------------------
#define KREG 80                  // k-values per gate held in registers
#define QSH  12                  // (128-KREG)/4 : ulonglong2 smem weight loads

__global__ __launch_bounds__(256, 1) void lstm_scan(
    const float* __restrict__ hprev,
    const float* __restrict__ cprev,
    const float* __restrict__ Whh,
    float* __restrict__ out)
{
    extern __shared__ __align__(16) float smdyn[];
    ulonglong2* wA = (ulonglong2*)smdyn;         // [QSH][256]
    ulonglong2* wB = wA + QSH * 256;             // [QSH][256]
    float* hbuf = (float*)(wB + QSH * 256);      // [2 buf][2 batch][128]
    float* gsm  = hbuf + 2 * 2 * 128;            // [2][512]

    const int tid = threadIdx.x;
    const int b0  = blockIdx.x * 2;
    const int gA  = tid;
    const int gB  = tid + 256;
    const int barid = 1 + ((tid >> 5) & 3);      // 2-warp group {w, w+4}

    #pragma unroll
    for (int q = 0; q < QSH; q++) {
        wA[q * 256 + tid] = *(const ulonglong2*)&Whh[gA * HH + KREG + 4 * q];
        wB[q * 256 + tid] = *(const ulonglong2*)&Whh[gB * HH + KREG + 4 * q];
    }

    ull wrA[KREG / 2], wrB[KREG / 2];
    #pragma unroll
    for (int p = 0; p < KREG / 2; p++) {
        wrA[p] = *(const ull*)&Whh[gA * HH + 2 * p];
        wrB[p] = *(const ull*)&Whh[gB * HH + 2 * p];
    }

    float* hc0 = hbuf;             // current, batch 0
    float* hc1 = hbuf + 128;       // current, batch 1
    float* hn0 = hbuf + 256;       // next,    batch 0
    float* hn1 = hbuf + 384;       // next,    batch 1

    const int b = tid >> 7, j = tid & 127;
    float h = hprev[(b0 + b) * HH + j];
    float c = cprev[(b0 + b) * HH + j];
    (b ? hc1 : hc0)[j] = h;
    __syncthreads();

    const float* xb0 = g_xg + (size_t)b0 * TT * GG;
    const float* xb1 = xb0 + (size_t)TT * GG;

    float x00 = xb0[tid], x01 = xb0[256 + tid];
    float x10 = xb1[tid], x11 = xb1[256 + tid];

    for (int t = 0; t < TT; t++) {
        size_t noff = (size_t)(t + 1 < TT ? t + 1 : t) * GG;
        float n00 = xb0[noff + tid], n01 = xb0[noff + 256 + tid];
        float n10 = xb1[noff + tid], n11 = xb1[noff + 256 + tid];

        ull aA0x = 0, aA0y = 0, aA1x = 0, aA1y = 0;
        ull aB0x = 0, aB0y = 0, aB1x = 0, aB1y = 0;

        #pragma unroll
        for (int q = 0; q < KREG / 4; q++) {
            ulonglong2 h0 = *(const ulonglong2*)&hc0[4 * q];
            ulonglong2 h1 = *(const ulonglong2*)&hc1[4 * q];
            ull w0 = wrA[2 * q], w1 = wrA[2 * q + 1];
            ull v0 = wrB[2 * q], v1 = wrB[2 * q + 1];
            aA0x = fma2(w0, h0.x, aA0x);  aA0y = fma2(w1, h0.y, aA0y);
            aA1x = fma2(w0, h1.x, aA1x);  aA1y = fma2(w1, h1.y, aA1y);
            aB0x = fma2(v0, h0.x, aB0x);  aB0y = fma2(v1, h0.y, aB0y);
            aB1x = fma2(v0, h1.x, aB1x);  aB1y = fma2(v1, h1.y, aB1y);
        }
        #pragma unroll
        for (int q = 0; q < QSH; q++) {
            ulonglong2 h0 = *(const ulonglong2*)&hc0[KREG + 4 * q];
            ulonglong2 h1 = *(const ulonglong2*)&hc1[KREG + 4 * q];
            ulonglong2 wa = wA[q * 256 + tid];
            ulonglong2 wb = wB[q * 256 + tid];
            aA0x = fma2(wa.x, h0.x, aA0x);  aA0y = fma2(wa.y, h0.y, aA0y);
            aA1x = fma2(wa.x, h1.x, aA1x);  aA1y = fma2(wa.y, h1.y, aA1y);
            aB0x = fma2(wb.x, h0.x, aB0x);  aB0y = fma2(wb.y, h0.y, aB0y);
            aB1x = fma2(wb.x, h1.x, aB1x);  aB1y = fma2(wb.y, h1.y, aB1y);
        }

        gsm[tid]             = x00 + hsum2(add2(aA0x, aA0y));
        gsm[256 + tid]       = x01 + hsum2(add2(aB0x, aB0y));
        gsm[512 + tid]       = x10 + hsum2(add2(aA1x, aA1y));
        gsm[512 + 256 + tid] = x11 + hsum2(add2(aB1x, aB1y));

        BAR_SYNC(barid, 64);

        {
            const float* gb = gsm + b * 512;
            float ig = fsig(gb[j]);             // PyTorch order: i, f, g, o
            float fg = fsig(gb[j + 128]);
            float gg = ftanh(gb[j + 256]);
            float og = fsig(gb[j + 384]);
            c = fg * c + ig * gg;
            h = og * ftanh(c);
            (b ? hn1 : hn0)[j] = h;
            out[((size_t)(b0 + b) * TT + t) * HH + j] = h;
        }
        __syncthreads();

        float* s0 = hc0; hc0 = hn0; hn0 = s0;
        float* s1 = hc1; hc1 = hn1; hn1 = s1;

        x00 = n00; x01 = n01; x10 = n10; x11 = n11;
    }

    {
        size_t base = (size_t)BB * TT * HH;
        out[base + (b0 + b) * HH + j] = h;
        out[base + (size_t)BB * HH + (b0 + b) * HH + j] = c;
    }
}

// ---------------------------------------------------------------------------
extern "C" void kernel_launch(void* const* d_in, const int* in_sizes, int n_in,
                              void* d_out, int out_size)
{
    const float* inputs = (const float*)d_in[0];
    const float* hprev  = (const float*)d_in[1];
    const float* cprev  = (const float*)d_in[2];
    const float* Wih    = (const float*)d_in[3];
    const float* Whh    = (const float*)d_in[4];
    const float* bih    = (const float*)d_in[5];
    const float* bhh    = (const float*)d_in[6];
    float* out = (float*)d_out;
    (void)in_sizes; (void)n_in; (void)out_size;

    const size_t smem1 = (size_t)(4 * 128 * QS) * sizeof(unsigned)
                       + (size_t)NQ * sizeof(float);                      // ~74 KB
    const size_t smem2 = (size_t)(2 * QSH * 256) * sizeof(ulonglong2)
                       + (size_t)(2 * 2 * 128 + 2 * 512) * sizeof(float); // ~104 KB
    cudaFuncSetAttribute(xg_gemm,   cudaFuncAttributeMaxDynamicSharedMemorySize, (int)smem1);
    cudaFuncSetAttribute(lstm_scan, cudaFuncAttributeMaxDynamicSharedMemorySize, (int)smem2);

    xg_gemm  <<<296, 256, smem1>>>(inputs, Wih, bih, bhh);
    lstm_scan<<<128, 256, smem2>>>(hprev, cprev, Whh, out);
}